// round 16
// baseline (speedup 1.0000x reference)
#include <cuda_runtime.h>
#include <math.h>

#define D 128
#define MAXN 100000
#define MAXE 600000
#define MAXEJ 300000
#define NB 512

// Scratch (allocation-free: static __device__ arrays)
__device__ float    g_h[(size_t)MAXN * D];  // hidden state h1 (f32)
__device__ unsigned g_xh[(size_t)MAXN * 64]; // emb as bf16x2 words
__device__ unsigned g_hh[(size_t)MAXN * 64]; // h1 as bf16x2 words
__device__ int   g_cnt[MAXN];
__device__ int   g_cntJ[MAXN];
__device__ int   g_rowptr[MAXN];
__device__ int   g_rowptrJ[MAXN];
__device__ int   g_cur[MAXN];
__device__ int   g_curJ[MAXN];
__device__ int   g_bsum[2][NB];
__device__ int   g_epack[MAXE];             // src | (type<<20)
__device__ int2  g_jpack[MAXEJ];            // (src, float bits of weight)

__device__ __forceinline__ unsigned pack_bf16(float lo, float hi) {
    unsigned r;
    asm("cvt.rn.bf16x2.f32 %0, %1, %2;" : "=r"(r) : "f"(hi), "f"(lo));
    return r;
}

// ---------------------------------------------------------------------------
// K0: copy change -> out[0:ND]; emb -> bf16 shadow; zero degree counters
// ---------------------------------------------------------------------------
__global__ void k_init(const float* __restrict__ change,
                       const float* __restrict__ emb,
                       float* __restrict__ out, int n) {
    int i = blockIdx.x * blockDim.x + threadIdx.x;
    int nd4 = n * (D / 4);
    if (i < nd4) {
        ((float4*)out)[i] = ((const float4*)change)[i];
        float4 e = ((const float4*)emb)[i];
        g_xh[2 * i]     = pack_bf16(e.x, e.y);
        g_xh[2 * i + 1] = pack_bf16(e.z, e.w);
    }
    if (i < n) { g_cnt[i] = 0; g_cntJ[i] = 0; }
}

// ---------------------------------------------------------------------------
// Histogram of destinations (conv + jump)
// ---------------------------------------------------------------------------
__global__ void k_hist(const int* __restrict__ ei, const int* __restrict__ ej,
                       int E, int EJ) {
    int i = blockIdx.x * blockDim.x + threadIdx.x;
    if (i < E)  atomicAdd(&g_cnt[ei[E + i]], 1);
    if (i < EJ) atomicAdd(&g_cntJ[ej[EJ + i]], 1);
}

// ---------------------------------------------------------------------------
// Exclusive scan, 3 kernels, blockIdx.y selects conv(0)/jump(1)
// ---------------------------------------------------------------------------
__global__ void k_scan1(int n) {
    __shared__ int s[256];
    const int y = blockIdx.y;
    const int* cnt = y ? g_cntJ : g_cnt;
    int* rp = y ? g_rowptrJ : g_rowptr;
    int idx = blockIdx.x * 256 + threadIdx.x;
    int v = (idx < n) ? cnt[idx] : 0;
    s[threadIdx.x] = v;
#pragma unroll
    for (int off = 1; off < 256; off <<= 1) {
        __syncthreads();
        int t = (threadIdx.x >= off) ? s[threadIdx.x - off] : 0;
        __syncthreads();
        s[threadIdx.x] += t;
    }
    __syncthreads();
    if (idx < n) rp[idx] = s[threadIdx.x] - v;
    if (threadIdx.x == 255) g_bsum[y][blockIdx.x] = s[255];
}

__global__ void k_scan2(int nb) {
    __shared__ int s[512];
    const int y = blockIdx.y;
    int v = (threadIdx.x < nb) ? g_bsum[y][threadIdx.x] : 0;
    s[threadIdx.x] = v;
#pragma unroll
    for (int off = 1; off < 512; off <<= 1) {
        __syncthreads();
        int t = (threadIdx.x >= off) ? s[threadIdx.x - off] : 0;
        __syncthreads();
        s[threadIdx.x] += t;
    }
    __syncthreads();
    if (threadIdx.x < nb) g_bsum[y][threadIdx.x] = s[threadIdx.x] - v;
}

__global__ void k_scan3(int n) {
    const int y = blockIdx.y;
    int* rp = y ? g_rowptrJ : g_rowptr;
    int* cur = y ? g_curJ : g_cur;
    int idx = blockIdx.x * 256 + threadIdx.x;
    if (idx < n) {
        int v = rp[idx] + g_bsum[y][blockIdx.x];
        rp[idx] = v;
        cur[idx] = v;
    }
}

// ---------------------------------------------------------------------------
// Permute edges into CSR order
// ---------------------------------------------------------------------------
__global__ void k_permute(const int* __restrict__ ei, const int* __restrict__ et,
                          const int* __restrict__ ej, const float* __restrict__ w,
                          int E, int EJ) {
    int i = blockIdx.x * blockDim.x + threadIdx.x;
    if (i < E) {
        int dst = ei[E + i];
        int pos = atomicAdd(&g_cur[dst], 1);
        g_epack[pos] = ei[i] | (et[i] << 20);
    }
    if (i < EJ) {
        int dst = ej[EJ + i];
        int pos = atomicAdd(&g_curJ[dst], 1);
        g_jpack[pos] = make_int2(ej[i], __float_as_int(w[i]));
    }
}

// ---------------------------------------------------------------------------
// Jump aggregation, pull-style (f32 emb, precision-critical path)
// ---------------------------------------------------------------------------
__global__ void k_aggj(const float* __restrict__ emb, float* __restrict__ outD,
                       int n) {
    int v = blockIdx.x * 8 + (threadIdx.x >> 5);
    int lane = threadIdx.x & 31;
    if (v >= n) return;
    int start = g_rowptrJ[v];
    int deg = g_cntJ[v];
    float4 acc = make_float4(0.f, 0.f, 0.f, 0.f);
    for (int base = 0; base < deg; base += 32) {
        int rem = deg - base;
        int cntc = rem < 32 ? rem : 32;
        int2 m = (lane < cntc) ? g_jpack[start + base + lane] : make_int2(0, 0);
        for (int j = 0; j < cntc; j++) {
            int src = __shfl_sync(0xffffffffu, m.x, j);
            float wv = __int_as_float(__shfl_sync(0xffffffffu, m.y, j));
            float4 xv = ((const float4*)emb)[(size_t)src * 32 + lane];
            acc.x += wv * xv.x; acc.y += wv * xv.y;
            acc.z += wv * xv.z; acc.w += wv * xv.w;
        }
    }
    ((float4*)outD)[(size_t)v * 32 + lane] = acc;
}

// ---------------------------------------------------------------------------
// Fused conv layer: CSR aggregation (bf16 gather) + bf16 mma GEMM + epilogue.
//   out[r] = xf[r] + res * tanh( (agg[r]/max(deg,1)) @ W + x[r] @ Wl )
//            (+ jw * jump[r]); optional bf16 shadow write of out.
// smem: sB 32KB (swizzled B, restaged W->Wl) | sAgg 64x68 words bf16x2
//       | sX 64x68 words bf16x2  => 67.6KB -> 3 CTAs/SM.
// ---------------------------------------------------------------------------
#define AG_STRIDE 68
#define SMEM_WORDS (64 * 128 + 64 * AG_STRIDE + 64 * AG_STRIDE)
#define SMEM_BYTES (SMEM_WORDS * 4)

__device__ __forceinline__ void mma_bf16(float* c, unsigned a0, unsigned a1,
                                         unsigned a2, unsigned a3,
                                         unsigned b0, unsigned b1) {
    asm("mma.sync.aligned.m16n8k16.row.col.f32.bf16.bf16.f32 "
        "{%0,%1,%2,%3}, {%4,%5,%6,%7}, {%8,%9}, {%0,%1,%2,%3};"
        : "+f"(c[0]), "+f"(c[1]), "+f"(c[2]), "+f"(c[3])
        : "r"(a0), "r"(a1), "r"(a2), "r"(a3), "r"(b0), "r"(b1));
}

__device__ __forceinline__ void edge_acc(int pm, const unsigned* __restrict__ xh,
                                         const float* __restrict__ rel, int lane,
                                         float& a0, float& a1, float& a2, float& a3) {
    int src = pm & 0xFFFFF;
    int t = ((unsigned)pm) >> 20;
    uint2 xv = ((const uint2*)xh)[(size_t)src * 32 + lane];
    float4 rv = ((const float4*)rel)[(size_t)t * 32 + lane];
    a0 += __uint_as_float(xv.x << 16) * rv.x;
    a1 += __uint_as_float(xv.x & 0xffff0000u) * rv.y;
    a2 += __uint_as_float(xv.y << 16) * rv.z;
    a3 += __uint_as_float(xv.y & 0xffff0000u) * rv.w;
}

__global__ __launch_bounds__(256, 3)
void k_gemm(const unsigned* __restrict__ xh,   // bf16 rows (gather + mainloop)
            const float* __restrict__ xf,      // f32 rows (epilogue residual)
            const float* __restrict__ rel,
            const float* __restrict__ W, const float* __restrict__ Wl,
            const float* __restrict__ resp, const float* __restrict__ jwp,
            const float* __restrict__ jumpbuf, float* __restrict__ out,
            unsigned* __restrict__ outh, int n) {
    extern __shared__ unsigned sm[];
    unsigned* sB   = sm;                        // 8192 words
    unsigned* sAgg = sm + 8192;                 // 4352 words
    unsigned* sX   = sm + 8192 + 4352;          // 4352 words

    const int tid = threadIdx.x;
    const int warp = tid >> 5, lane = tid & 31;
    const int grp = lane >> 2, tig = lane & 3;
    const int mw = warp >> 2;        // 0..1 (m half)
    const int nw = warp & 3;         // 0..3 (n quarter)
    const int rbase = mw * 32 + grp;

    // ---- stage B = W (bf16x2, swizzled) ----
#pragma unroll
    for (int t = 0; t < 8; t++) {
        int j = tid + t * 256;
        int kw = j >> 5, c4 = j & 31;
        float4 w0 = ((const float4*)W)[(2 * kw) * 32 + c4];
        float4 w1 = ((const float4*)W)[(2 * kw + 1) * 32 + c4];
        uint4 u;
        u.x = pack_bf16(w0.x, w1.x); u.y = pack_bf16(w0.y, w1.y);
        u.z = pack_bf16(w0.z, w1.z); u.w = pack_bf16(w0.w, w1.w);
        int off = (c4 * 4 + ((kw & 3) << 3)) & 127;
        *(uint4*)(sB + kw * 128 + off) = u;
    }

    // ---- stage sX: direct bf16 copy of this CTA's 64 x rows ----
#pragma unroll
    for (int t = 0; t < 4; t++) {
        int j = tid + t * 256;          // 0..1023; uint4 per thread-slot
        int row = j >> 4, w4 = j & 15;
        int grow = blockIdx.x * 64 + row;
        uint4 v = make_uint4(0u, 0u, 0u, 0u);
        if (grow < n) v = ((const uint4*)xh)[(size_t)grow * 16 + w4];
        *(uint4*)(sX + row * AG_STRIDE + w4 * 4) = v;
    }

    // ---- CSR aggregation: 8 rows per warp -> sAgg (deg-scaled bf16) ----
#pragma unroll 1
    for (int rr = 0; rr < 8; rr++) {
        int row = warp * 8 + rr;
        int v = blockIdx.x * 64 + row;
        float a0 = 0.f, a1 = 0.f, a2 = 0.f, a3 = 0.f;
        if (v < n) {
            int start = g_rowptr[v];
            int deg = g_cnt[v];
#pragma unroll 1
            for (int base = 0; base < deg; base += 32) {
                int rem = deg - base;
                int cntc = rem < 32 ? rem : 32;
                int m = (lane < cntc) ? g_epack[start + base + lane] : 0;
                int j = 0;
                for (; j + 4 <= cntc; j += 4) {
                    int p0 = __shfl_sync(0xffffffffu, m, j);
                    int p1 = __shfl_sync(0xffffffffu, m, j + 1);
                    int p2 = __shfl_sync(0xffffffffu, m, j + 2);
                    int p3 = __shfl_sync(0xffffffffu, m, j + 3);
                    edge_acc(p0, xh, rel, lane, a0, a1, a2, a3);
                    edge_acc(p1, xh, rel, lane, a0, a1, a2, a3);
                    edge_acc(p2, xh, rel, lane, a0, a1, a2, a3);
                    edge_acc(p3, xh, rel, lane, a0, a1, a2, a3);
                }
                for (; j < cntc; j++) {
                    int p = __shfl_sync(0xffffffffu, m, j);
                    edge_acc(p, xh, rel, lane, a0, a1, a2, a3);
                }
            }
            float s = 1.0f / fmaxf((float)deg, 1.0f);
            a0 *= s; a1 *= s; a2 *= s; a3 *= s;
        }
        sAgg[row * AG_STRIDE + lane * 2]     = pack_bf16(a0, a1);
        sAgg[row * AG_STRIDE + lane * 2 + 1] = pack_bf16(a2, a3);
    }
    __syncthreads();

    float acc[8][4];
#pragma unroll
    for (int i = 0; i < 8; i++)
#pragma unroll
        for (int q = 0; q < 4; q++) acc[i][q] = 0.f;

    const int bbase = nw * 32 + grp + tig * 8;

    // ---- pass 0: agg @ W ----
#pragma unroll
    for (int ks = 0; ks < 8; ks++) {
        const int aw = ks * 8 + tig;
        unsigned a00 = sAgg[(rbase)      * AG_STRIDE + aw];
        unsigned a01 = sAgg[(rbase + 8)  * AG_STRIDE + aw];
        unsigned a02 = sAgg[(rbase)      * AG_STRIDE + aw + 4];
        unsigned a03 = sAgg[(rbase + 8)  * AG_STRIDE + aw + 4];
        unsigned a10 = sAgg[(rbase + 16) * AG_STRIDE + aw];
        unsigned a11 = sAgg[(rbase + 24) * AG_STRIDE + aw];
        unsigned a12 = sAgg[(rbase + 16) * AG_STRIDE + aw + 4];
        unsigned a13 = sAgg[(rbase + 24) * AG_STRIDE + aw + 4];
        const unsigned* pb = sB + (ks * 8 + tig) * 128;
#pragma unroll
        for (int nt = 0; nt < 4; nt++) {
            int col = (bbase + nt * 8) & 127;
            unsigned b0 = pb[col];
            unsigned b1 = pb[512 + col];
            mma_bf16(acc[nt],     a00, a01, a02, a03, b0, b1);
            mma_bf16(acc[4 + nt], a10, a11, a12, a13, b0, b1);
        }
    }
    __syncthreads();

    // ---- restage B = Wl ----
#pragma unroll
    for (int t = 0; t < 8; t++) {
        int j = tid + t * 256;
        int kw = j >> 5, c4 = j & 31;
        float4 w0 = ((const float4*)Wl)[(2 * kw) * 32 + c4];
        float4 w1 = ((const float4*)Wl)[(2 * kw + 1) * 32 + c4];
        uint4 u;
        u.x = pack_bf16(w0.x, w1.x); u.y = pack_bf16(w0.y, w1.y);
        u.z = pack_bf16(w0.z, w1.z); u.w = pack_bf16(w0.w, w1.w);
        int off = (c4 * 4 + ((kw & 3) << 3)) & 127;
        *(uint4*)(sB + kw * 128 + off) = u;
    }
    __syncthreads();

    // ---- pass 1: x @ Wl ----
#pragma unroll
    for (int ks = 0; ks < 8; ks++) {
        const int aw = ks * 8 + tig;
        unsigned a00 = sX[(rbase)      * AG_STRIDE + aw];
        unsigned a01 = sX[(rbase + 8)  * AG_STRIDE + aw];
        unsigned a02 = sX[(rbase)      * AG_STRIDE + aw + 4];
        unsigned a03 = sX[(rbase + 8)  * AG_STRIDE + aw + 4];
        unsigned a10 = sX[(rbase + 16) * AG_STRIDE + aw];
        unsigned a11 = sX[(rbase + 24) * AG_STRIDE + aw];
        unsigned a12 = sX[(rbase + 16) * AG_STRIDE + aw + 4];
        unsigned a13 = sX[(rbase + 24) * AG_STRIDE + aw + 4];
        const unsigned* pb = sB + (ks * 8 + tig) * 128;
#pragma unroll
        for (int nt = 0; nt < 4; nt++) {
            int col = (bbase + nt * 8) & 127;
            unsigned b0 = pb[col];
            unsigned b1 = pb[512 + col];
            mma_bf16(acc[nt],     a00, a01, a02, a03, b0, b1);
            mma_bf16(acc[4 + nt], a10, a11, a12, a13, b0, b1);
        }
    }

    // ---- epilogue ----
    const float res = resp[0];
    const float jw = jwp ? jwp[0] : 0.f;
#pragma unroll
    for (int mt = 0; mt < 2; mt++) {
        const int r0 = blockIdx.x * 64 + mw * 32 + mt * 16 + grp;
        const int r1 = r0 + 8;
        const bool v0 = r0 < n, v1 = r1 < n;
#pragma unroll
        for (int nt = 0; nt < 4; nt++) {
            const int cc = nw * 32 + nt * 8 + tig * 2;
            const float* a = acc[mt * 4 + nt];
            if (v0) {
                float2 xv = *(const float2*)(xf + (size_t)r0 * 128 + cc);
                float o0 = xv.x + res * tanhf(a[0]);
                float o1 = xv.y + res * tanhf(a[1]);
                if (jumpbuf) {
                    float2 jv = *(const float2*)(jumpbuf + (size_t)r0 * 128 + cc);
                    o0 += jw * jv.x; o1 += jw * jv.y;
                }
                *(float2*)(out + (size_t)r0 * 128 + cc) = make_float2(o0, o1);
                if (outh) outh[(size_t)r0 * 64 + (cc >> 1)] = pack_bf16(o0, o1);
            }
            if (v1) {
                float2 xv = *(const float2*)(xf + (size_t)r1 * 128 + cc);
                float o0 = xv.x + res * tanhf(a[2]);
                float o1 = xv.y + res * tanhf(a[3]);
                if (jumpbuf) {
                    float2 jv = *(const float2*)(jumpbuf + (size_t)r1 * 128 + cc);
                    o0 += jw * jv.x; o1 += jw * jv.y;
                }
                *(float2*)(out + (size_t)r1 * 128 + cc) = make_float2(o0, o1);
                if (outh) outh[(size_t)r1 * 64 + (cc >> 1)] = pack_bf16(o0, o1);
            }
        }
    }
}

// ---------------------------------------------------------------------------
// Launch sequence (graph-capturable: kernel launches only)
// ---------------------------------------------------------------------------
extern "C" void kernel_launch(void* const* d_in, const int* in_sizes, int n_in,
                              void* d_out, int out_size) {
    const float* emb    = (const float*)d_in[0];
    const float* change = (const float*)d_in[1];
    const float* W1     = (const float*)d_in[2];
    const float* Wl1    = (const float*)d_in[3];
    const float* rel1   = (const float*)d_in[4];
    const float* W2     = (const float*)d_in[5];
    const float* Wl2    = (const float*)d_in[6];
    const float* rel2   = (const float*)d_in[7];
    const float* res    = (const float*)d_in[8];
    const float* jw     = (const float*)d_in[9];
    const float* ewj    = (const float*)d_in[10];
    const int*   ei     = (const int*)d_in[11];
    const int*   et     = (const int*)d_in[12];
    const int*   ej     = (const int*)d_in[13];

    const int N  = in_sizes[0] / 128;
    const int E  = in_sizes[12];
    const int EJ = in_sizes[10];
    if (N <= 0 || E <= 0 || EJ <= 0) return;

    float* out  = (float*)d_out;
    float* outD = out + (size_t)N * 128;

    float* hptr = nullptr;
    unsigned* xhptr = nullptr;
    unsigned* hhptr = nullptr;
    cudaGetSymbolAddress((void**)&hptr, g_h);
    cudaGetSymbolAddress((void**)&xhptr, g_xh);
    cudaGetSymbolAddress((void**)&hhptr, g_hh);

    cudaFuncSetAttribute(k_gemm, cudaFuncAttributeMaxDynamicSharedMemorySize, SMEM_BYTES);

    const int nd4 = N * 32;
    const int emax = E > EJ ? E : EJ;
    const int nb = (N + 255) / 256;
    dim3 gscan(nb, 2);

    // init + CSR build (conv CSR reused by both layers)
    k_init<<<(nd4 + 255) / 256, 256>>>(change, emb, out, N);
    k_hist<<<(emax + 255) / 256, 256>>>(ei, ej, E, EJ);
    k_scan1<<<gscan, 256>>>(N);
    k_scan2<<<dim3(1, 2), 512>>>(nb);
    k_scan3<<<gscan, 256>>>(N);
    k_permute<<<(emax + 255) / 256, 256>>>(ei, et, ej, ewj, E, EJ);

    // jump aggregation into dchange half (f32 path)
    k_aggj<<<(N + 7) / 8, 256>>>(emb, outD, N);

    const int gB = (N + 63) / 64;
    // layer 1 (fused agg+gemm): h = emb + res*tanh(...); also writes h-bf16
    k_gemm<<<gB, 256, SMEM_BYTES>>>(xhptr, emb, rel1, W1, Wl1, res,
                                    nullptr, nullptr, hptr, hhptr, N);
    // layer 2 (fused agg+gemm): dchange = h + res*tanh(...) + jw*jump
    k_gemm<<<gB, 256, SMEM_BYTES>>>(hhptr, hptr, rel2, W2, Wl2, res,
                                    jw, outD, outD, nullptr, N);
}